// round 5
// baseline (speedup 1.0000x reference)
#include <cuda_runtime.h>
#include <math.h>

// Problem constants
#define Bn    64
#define Cc    128
#define HWn   3136            // 56*56
#define MTOT  (Bn*HWn)        // 200704
#define NPART 148
#define CHUNK 1357            // ceil(MTOT/NPART); 148*1357 = 200836 >= 200704
#define EPSV  1e-5f

// ---------------- device scratch (static, no allocation) ----------------
// g_bufs: 0=P 1=T1 2=T2 3=Sigma 4=M
__device__ float g_bufs[5][Cc*Cc];
__device__ float g_partS[NPART*Cc*Cc];   // ~9.7 MB
__device__ float g_partsum[NPART*Cc];
__device__ float g_mean[Cc];
__device__ float g_bias[Cc];
__device__ float g_scal[2];              // [0]=rTr, [1]=sqrt(rTr)

// =========================================================================
// Kernel 1: partial covariance (raw second moment) + partial channel sums
// grid = NPART CTAs, 256 threads. Each CTA handles columns [p*CHUNK, ...).
// Per-thread 8x8 register tile of the 128x128 moment matrix.
// =========================================================================
__global__ __launch_bounds__(256) void k_cov(const float* __restrict__ x) {
    __shared__ float xs[16*132];   // [kk][c], padded row 132 (16B aligned rows)
    const int t  = threadIdx.x;
    const int p  = blockIdx.x;
    const int n0 = p * CHUNK;
    const int n1 = min(n0 + CHUNK, MTOT);

    float acc[8][8];
#pragma unroll
    for (int i = 0; i < 8; i++)
#pragma unroll
        for (int j = 0; j < 8; j++) acc[i][j] = 0.f;
    float sacc = 0.f;

    const int kk = t & 15;
    const int cb = t >> 4;
    const int r0 = (t >> 4) * 8;
    const int c0 = (t & 15) * 8;

    for (int nt = n0; nt < n1; nt += 16) {
        __syncthreads();
        // ---- load 128 channels x 16 columns (transposed into [kk][c]) ----
        const int n = nt + kk;
        if (n < n1) {
            const int b  = n / HWn;
            const int hw = n - b * HWn;
            const float* xp = x + (size_t)b * Cc * HWn + hw;
#pragma unroll
            for (int j = 0; j < 8; j++) {
                const int c = cb + j * 16;
                xs[kk*132 + c] = xp[(size_t)c * HWn];
            }
        } else {
#pragma unroll
            for (int j = 0; j < 8; j++) xs[kk*132 + cb + j*16] = 0.f;
        }
        __syncthreads();

        // ---- channel sums (threads 0..127 own one channel each) ----
        if (t < Cc) {
#pragma unroll
            for (int q = 0; q < 16; q++) sacc += xs[q*132 + t];
        }

        // ---- 8x8 outer-product accumulation over 16 k steps ----
#pragma unroll
        for (int k = 0; k < 16; k++) {
            float4 a0 = *(const float4*)&xs[k*132 + r0];
            float4 a1 = *(const float4*)&xs[k*132 + r0 + 4];
            float4 b0 = *(const float4*)&xs[k*132 + c0];
            float4 b1 = *(const float4*)&xs[k*132 + c0 + 4];
            float av[8] = {a0.x,a0.y,a0.z,a0.w,a1.x,a1.y,a1.z,a1.w};
            float bv[8] = {b0.x,b0.y,b0.z,b0.w,b1.x,b1.y,b1.z,b1.w};
#pragma unroll
            for (int i = 0; i < 8; i++)
#pragma unroll
                for (int j = 0; j < 8; j++) acc[i][j] += av[i] * bv[j];
        }
    }

    // ---- write partials ----
    float* outp = g_partS + (size_t)p * Cc * Cc;
#pragma unroll
    for (int i = 0; i < 8; i++) {
        float4 v0 = make_float4(acc[i][0], acc[i][1], acc[i][2], acc[i][3]);
        float4 v1 = make_float4(acc[i][4], acc[i][5], acc[i][6], acc[i][7]);
        *(float4*)&outp[(r0+i)*Cc + c0    ] = v0;
        *(float4*)&outp[(r0+i)*Cc + c0 + 4] = v1;
    }
    if (t < Cc) g_partsum[p*Cc + t] = sacc;
}

// =========================================================================
// Small reduction / setup kernels (all deterministic fixed-order)
// =========================================================================
__global__ void k_meanred() {           // <<<1,128>>>
    const int c = threadIdx.x;
    float s = 0.f;
    for (int p = 0; p < NPART; p++) s += g_partsum[p*Cc + c];
    g_mean[c] = s / (float)MTOT;
}

__global__ void k_sigred() {            // <<<128,128>>>  Sigma row per CTA
    const int i = blockIdx.x, j = threadIdx.x;
    float s = 0.f;
    for (int p = 0; p < NPART; p++) s += g_partS[(size_t)p*Cc*Cc + i*Cc + j];
    float v = s / (float)MTOT - g_mean[i]*g_mean[j];
    if (i == j) v += EPSV;
    g_bufs[3][i*Cc + j] = v;
}

__global__ void k_trace_init() {        // <<<1,256>>>  trace -> scal, P = I
    __shared__ float red[128];
    const int t = threadIdx.x;
    if (t < 128) red[t] = g_bufs[3][t*129];
    __syncthreads();
    for (int s = 64; s > 0; s >>= 1) {
        if (t < s) red[t] += red[t+s];
        __syncthreads();
    }
    if (t == 0) {
        float rTr = 1.f / red[0];
        g_scal[0] = rTr;
        g_scal[1] = sqrtf(rTr);
    }
    for (int idx = t; idx < Cc*Cc; idx += 256)
        g_bufs[0][idx] = ((idx >> 7) == (idx & 127)) ? 1.f : 0.f;
}

// =========================================================================
// 128x128x128 fp32 matmul, grid = 16 CTAs (8 rows each), 256 threads.
// mode 0: Cout = A*B
// mode 1: Cout = 1.5*Cin - 0.5*rTr*(A*B)      (Newton P update)
// mode 2: Cout = sqrt(rTr)*(A*B)              (M = rot * wm)
// Operands selected by index into g_bufs; ia==5 means A = rot (input ptr).
// =========================================================================
__global__ __launch_bounds__(256) void k_mm(int ia, int ib, int ic, int io,
                                            int mode, const float* __restrict__ rot) {
    __shared__ float As[8*128];
    __shared__ float Bs[32*128];
    const float* A   = (ia == 5) ? rot : g_bufs[ia];
    const float* Bm  = g_bufs[ib];
    const float* Cin = g_bufs[ic];
    float*       Cout= g_bufs[io];

    const int t   = threadIdx.x;
    const int blk = blockIdx.x;            // 8 output rows per CTA

    // load this CTA's 8 rows of A (contiguous 1024 floats)
    *(float4*)&As[t*4] = *(const float4*)(A + blk*8*128 + t*4);

    const int c  = t & 127;
    const int rg = t >> 7;                 // 0/1: rows rg*4 .. rg*4+3
    float acc[4] = {0.f,0.f,0.f,0.f};

    for (int kb = 0; kb < 4; kb++) {
        __syncthreads();
#pragma unroll
        for (int i = 0; i < 4; i++) {
            const int flat = i*1024 + t*4;
            *(float4*)&Bs[flat] = *(const float4*)(Bm + kb*32*128 + flat);
        }
        __syncthreads();
#pragma unroll
        for (int k = 0; k < 32; k++) {
            const float bv = Bs[k*128 + c];
#pragma unroll
            for (int i = 0; i < 4; i++)
                acc[i] += As[(rg*4+i)*128 + kb*32 + k] * bv;
        }
    }

    const float s0 = g_scal[0], s1 = g_scal[1];
#pragma unroll
    for (int i = 0; i < 4; i++) {
        const int r   = blk*8 + rg*4 + i;
        const int idx = r*128 + c;
        float v = acc[i];
        if (mode == 0)       Cout[idx] = v;
        else if (mode == 1)  Cout[idx] = 1.5f*Cin[idx] - 0.5f*s0*v;
        else                 Cout[idx] = s1*v;
    }
}

__global__ void k_bias() {              // <<<1,128>>>  bias = M @ mean
    __shared__ float mn[128];
    const int t = threadIdx.x;
    mn[t] = g_mean[t];
    __syncthreads();
    float s = 0.f;
    const float* Mrow = g_bufs[4] + t*Cc;
    for (int cidx = 0; cidx < Cc; cidx++) s += Mrow[cidx] * mn[cidx];
    g_bias[t] = s;
}

// =========================================================================
// Kernel: out[b,d,hw] = sum_c M[d,c]*x[b,c,hw] - bias[d]
// grid = (49 hw-tiles of 64, 64 batches), 256 threads.
// CTA tile: 128 d x 64 hw; thread tile 8x4; K chunked by 32.
// =========================================================================
__global__ __launch_bounds__(256) void k_transform(const float* __restrict__ x,
                                                   float* __restrict__ out) {
    __shared__ float Ms[32*132];   // M^T chunk [k][d], padded
    __shared__ float Xs[32*64];    // x chunk  [k][hw]
    const int t   = threadIdx.x;
    const int hw0 = blockIdx.x * 64;
    const int b   = blockIdx.y;
    const float* xb = x   + (size_t)b * Cc * HWn;
    float*       ob = out + (size_t)b * Cc * HWn;

    const int tx = t & 15, ty = t >> 4;
    const int r0 = ty * 8, c0 = tx * 4;
    float acc[8][4];
#pragma unroll
    for (int i = 0; i < 8; i++)
#pragma unroll
        for (int j = 0; j < 4; j++) acc[i][j] = 0.f;

    const float* Mg = g_bufs[4];

    for (int kb = 0; kb < 4; kb++) {
        __syncthreads();
        // M chunk, transposed into smem
#pragma unroll
        for (int i = 0; i < 16; i++) {
            const int flat = i*256 + t;          // 0..4095
            const int d  = flat >> 5;
            const int kk = flat & 31;
            Ms[kk*132 + d] = Mg[d*Cc + kb*32 + kk];
        }
        // X chunk (float4 along hw)
#pragma unroll
        for (int i = 0; i < 2; i++) {
            const int v  = i*256 + t;            // 0..511
            const int kk = v >> 4;
            const int c4 = (v & 15) * 4;
            float4 val = *(const float4*)(xb + (size_t)(kb*32+kk)*HWn + hw0 + c4);
            *(float4*)&Xs[kk*64 + c4] = val;
        }
        __syncthreads();
#pragma unroll
        for (int k = 0; k < 32; k++) {
            float4 a0 = *(const float4*)&Ms[k*132 + r0];
            float4 a1 = *(const float4*)&Ms[k*132 + r0 + 4];
            float4 bv = *(const float4*)&Xs[k*64 + c0];
            float av[8] = {a0.x,a0.y,a0.z,a0.w,a1.x,a1.y,a1.z,a1.w};
#pragma unroll
            for (int i = 0; i < 8; i++) {
                acc[i][0] += av[i]*bv.x;
                acc[i][1] += av[i]*bv.y;
                acc[i][2] += av[i]*bv.z;
                acc[i][3] += av[i]*bv.w;
            }
        }
    }

#pragma unroll
    for (int i = 0; i < 8; i++) {
        const int d = r0 + i;
        const float bi = g_bias[d];
        float4 o = make_float4(acc[i][0]-bi, acc[i][1]-bi, acc[i][2]-bi, acc[i][3]-bi);
        *(float4*)(ob + (size_t)d*HWn + hw0 + c0) = o;
    }
}

// =========================================================================
extern "C" void kernel_launch(void* const* d_in, const int* in_sizes, int n_in,
                              void* d_out, int out_size) {
    const float* x   = (const float*)d_in[0];
    const float* rot = (const float*)d_in[1];
    float* out = (float*)d_out;
    (void)in_sizes; (void)n_in; (void)out_size;

    k_cov<<<NPART, 256>>>(x);
    k_meanred<<<1, 128>>>();
    k_sigred<<<128, 128>>>();
    k_trace_init<<<1, 256>>>();

    // Newton iterations: P <- 1.5 P - 0.5 * rTr * (((P*P)*P)*Sigma)
    for (int it = 0; it < 5; it++) {
        k_mm<<<16, 256>>>(0, 0, 0, 1, 0, rot);   // T1 = P*P
        k_mm<<<16, 256>>>(1, 0, 0, 2, 0, rot);   // T2 = T1*P
        k_mm<<<16, 256>>>(2, 3, 0, 0, 1, rot);   // P  = 1.5P - 0.5*rTr*(T2*Sigma)
    }
    // M = sqrt(rTr) * rot * P
    k_mm<<<16, 256>>>(5, 0, 0, 4, 2, rot);
    k_bias<<<1, 128>>>();

    dim3 tg(HWn/64, Bn);
    k_transform<<<tg, 256>>>(x, out);
}

// round 10
// speedup vs baseline: 1.4705x; 1.4705x over previous
#include <cuda_runtime.h>
#include <cuda_bf16.h>
#include <cstdint>
#include <math.h>

#define Bn    64
#define Cc    128
#define HWn   3136
#define MTOT  (Bn*HWn)
#define NCOV  148
#define EPSV  1e-5f

// ---------------- device scratch ----------------
__device__ float g_pS1[NCOV*Cc*Cc];
__device__ float g_pS2[NCOV*Cc*Cc];
__device__ float g_psum[NCOV*Cc];
__device__ float g_bufs[5][Cc*Cc];      // 0=P 1=T1 2=T2 3=Sigma 4=M
__device__ float g_mean[Cc];
__device__ float g_bias[Cc];
__device__ float g_scal[2];
__device__ __align__(4) __nv_bfloat16 g_Mh[Cc*Cc];
__device__ __align__(4) __nv_bfloat16 g_Ml[Cc*Cc];

// ---------------- helpers ----------------
__device__ __forceinline__ uint32_t smem_u32(const void* p) {
    uint32_t a;
    asm("{ .reg .u64 t; cvta.to.shared.u64 t, %1; cvt.u32.u64 %0, t; }" : "=r"(a) : "l"(p));
    return a;
}
#define SWZ(x) ((x) ^ (((x) >> 3) & 0x70))

#define LDM_X4(r0,r1,r2,r3,addr) \
    asm volatile("ldmatrix.sync.aligned.m8n8.x4.shared.b16 {%0,%1,%2,%3}, [%4];" \
        : "=r"(r0),"=r"(r1),"=r"(r2),"=r"(r3) : "r"(addr))
#define LDM_X2(r0,r1,addr) \
    asm volatile("ldmatrix.sync.aligned.m8n8.x2.shared.b16 {%0,%1}, [%2];" \
        : "=r"(r0),"=r"(r1) : "r"(addr))
#define LDM_X2T(r0,r1,addr) \
    asm volatile("ldmatrix.sync.aligned.m8n8.x2.trans.shared.b16 {%0,%1}, [%2];" \
        : "=r"(r0),"=r"(r1) : "r"(addr))
#define MMA16816(d,a0,a1,a2,a3,b0,b1) \
    asm volatile("mma.sync.aligned.m16n8k16.row.col.f32.bf16.bf16.f32 " \
        "{%0,%1,%2,%3}, {%4,%5,%6,%7}, {%8,%9}, {%0,%1,%2,%3};" \
        : "+f"((d)[0]),"+f"((d)[1]),"+f"((d)[2]),"+f"((d)[3]) \
        : "r"(a0),"r"(a1),"r"(a2),"r"(a3),"r"(b0),"r"(b1))

__device__ __forceinline__ uint32_t packbf(__nv_bfloat16 a, __nv_bfloat16 b) {
    return ((uint32_t)__bfloat16_as_ushort(b) << 16) | (uint32_t)__bfloat16_as_ushort(a);
}

// load one 128(ch) x 64(sample) tile of x, split fp32 -> bf16 hi/lo into swizzled smem
// rows: 64 bf16 = 128 bytes, SWZ within tile. Optionally accumulates channel sums.
__device__ __forceinline__ void load_tile(const float* __restrict__ x, int ti,
                                          char* hb, char* lb, float* sacc) {
    const int b = ti / 49;
    const int hw0 = (ti - b * 49) * 64;
    const int t = threadIdx.x;
#pragma unroll
    for (int i = 0; i < 8; i++) {
        const int q = i * 256 + t;
        const int r = q >> 4, c4 = q & 15;
        const float4 v = *(const float4*)(x + ((size_t)(b * Cc + r)) * HWn + hw0 + c4 * 4);
        if (sacc) sacc[i] += (v.x + v.y) + (v.z + v.w);
        __nv_bfloat16 h0 = __float2bfloat16(v.x), h1 = __float2bfloat16(v.y);
        __nv_bfloat16 h2 = __float2bfloat16(v.z), h3 = __float2bfloat16(v.w);
        uint2 ph; ph.x = packbf(h0, h1); ph.y = packbf(h2, h3);
        __nv_bfloat16 l0 = __float2bfloat16(v.x - __bfloat162float(h0));
        __nv_bfloat16 l1 = __float2bfloat16(v.y - __bfloat162float(h1));
        __nv_bfloat16 l2 = __float2bfloat16(v.z - __bfloat162float(h2));
        __nv_bfloat16 l3 = __float2bfloat16(v.w - __bfloat162float(h3));
        uint2 pl; pl.x = packbf(l0, l1); pl.y = packbf(l2, l3);
        const uint32_t off = SWZ((uint32_t)(r * 128 + c4 * 8));
        *(uint2*)(hb + off) = ph;
        *(uint2*)(lb + off) = pl;
    }
}

// =========================================================================
// k_cov: HMMA SYRK partials. warps 0-3: S1 = Xh*Xh^T, warps 4-7: S2 = Xh*Xl^T
// each warp: 32 output rows x 128 cols, fp32 register accumulators.
// =========================================================================
__global__ __launch_bounds__(256, 1) void k_cov(const float* __restrict__ x) {
    __shared__ __align__(128) char hb[16384];
    __shared__ __align__(128) char lb[16384];
    const int t = threadIdx.x, p = blockIdx.x;
    const int w = t >> 5, l = t & 31;

    const int t0  = p * 21 + min(p, 28);
    const int cnt = 21 + (p < 28 ? 1 : 0);

    float sacc[8];
#pragma unroll
    for (int i = 0; i < 8; i++) sacc[i] = 0.f;

    float d[2][16][4];
#pragma unroll
    for (int b2 = 0; b2 < 2; b2++)
#pragma unroll
        for (int j = 0; j < 16; j++)
#pragma unroll
            for (int q = 0; q < 4; q++) d[b2][j][q] = 0.f;

    const uint32_t hba = smem_u32(hb);
    const uint32_t bba = (w >= 4) ? smem_u32(lb) : hba;   // S2 warps use lo as B
    const int rbase = (w & 3) * 32;

    for (int i = 0; i < cnt; i++) {
        load_tile(x, t0 + i, hb, lb, sacc);
        __syncthreads();
#pragma unroll
        for (int ks = 0; ks < 4; ks++) {
            uint32_t a[2][4];
#pragma unroll
            for (int blk = 0; blk < 2; blk++) {
                const uint32_t ao = hba + SWZ((uint32_t)((rbase + blk*16 + (l & 15))*128
                                              + ks*32 + (l >> 4)*16));
                LDM_X4(a[blk][0], a[blk][1], a[blk][2], a[blk][3], ao);
            }
#pragma unroll
            for (int jb = 0; jb < 16; jb++) {
                uint32_t b0, b1;
                const uint32_t bo = bba + SWZ((uint32_t)((jb*8 + (l & 7))*128
                                              + ks*32 + ((l >> 3) & 1)*16));
                LDM_X2(b0, b1, bo);
                MMA16816(d[0][jb], a[0][0], a[0][1], a[0][2], a[0][3], b0, b1);
                MMA16816(d[1][jb], a[1][0], a[1][1], a[1][2], a[1][3], b0, b1);
            }
        }
        __syncthreads();
    }

    // write partials
    float* dst = ((w >= 4) ? g_pS2 : g_pS1) + (size_t)p * 16384;
#pragma unroll
    for (int blk = 0; blk < 2; blk++) {
#pragma unroll
        for (int jb = 0; jb < 16; jb++) {
            const int r0 = rbase + blk*16 + (l >> 2);
            const int c  = jb*8 + (l & 3)*2;
            *(float2*)&dst[r0*128 + c]       = make_float2(d[blk][jb][0], d[blk][jb][1]);
            *(float2*)&dst[(r0 + 8)*128 + c] = make_float2(d[blk][jb][2], d[blk][jb][3]);
        }
    }

    // mean partials: threads in 16-groups share a channel
#pragma unroll
    for (int i = 0; i < 8; i++) {
#pragma unroll
        for (int off = 8; off > 0; off >>= 1)
            sacc[i] += __shfl_down_sync(0xffffffffu, sacc[i], off, 16);
    }
    if ((t & 15) == 0) {
#pragma unroll
        for (int i = 0; i < 8; i++) g_psum[p * Cc + i * 16 + (t >> 4)] = sacc[i];
    }
}

// =========================================================================
// small reduction / setup kernels (proven fp32 chain)
// =========================================================================
__global__ void k_meanred() {           // <<<1,128>>>
    const int c = threadIdx.x;
    float s = 0.f;
    for (int p = 0; p < NCOV; p++) s += g_psum[p*Cc + c];
    g_mean[c] = s / (float)MTOT;
}

__global__ void k_sigred() {            // <<<128,128>>>
    const int i = blockIdx.x, j = threadIdx.x;
    float s = 0.f, st = 0.f;
    for (int p = 0; p < NCOV; p++) {
        const size_t base = (size_t)p * 16384;
        s  += g_pS1[base + i*128 + j] + g_pS2[base + i*128 + j];
        st += g_pS2[base + j*128 + i];
    }
    float v = (s + st) / (float)MTOT - g_mean[i]*g_mean[j];
    if (i == j) v += EPSV;
    g_bufs[3][i*Cc + j] = v;
}

__global__ void k_trace_init() {        // <<<1,256>>>
    __shared__ float red[128];
    const int t = threadIdx.x;
    if (t < 128) red[t] = g_bufs[3][t*129];
    __syncthreads();
    for (int s = 64; s > 0; s >>= 1) {
        if (t < s) red[t] += red[t+s];
        __syncthreads();
    }
    if (t == 0) {
        float rTr = 1.f / red[0];
        g_scal[0] = rTr;
        g_scal[1] = sqrtf(rTr);
    }
    for (int idx = t; idx < Cc*Cc; idx += 256)
        g_bufs[0][idx] = ((idx >> 7) == (idx & 127)) ? 1.f : 0.f;
}

// 128^3 fp32 matmul (proven). mode 0: C=A*B; 1: C=1.5*Cin-0.5*rTr*(A*B); 2: C=sqrt(rTr)*(A*B)
__global__ __launch_bounds__(256) void k_mm(int ia, int ib, int ic, int io,
                                            int mode, const float* __restrict__ rot) {
    __shared__ float As[8*128];
    __shared__ float Bs[32*128];
    const float* A   = (ia == 5) ? rot : g_bufs[ia];
    const float* Bm  = g_bufs[ib];
    const float* Cin = g_bufs[ic];
    float*       Cout= g_bufs[io];
    const int t = threadIdx.x, blk = blockIdx.x;
    *(float4*)&As[t*4] = *(const float4*)(A + blk*8*128 + t*4);
    const int c = t & 127, rg = t >> 7;
    float acc[4] = {0.f,0.f,0.f,0.f};
    for (int kb = 0; kb < 4; kb++) {
        __syncthreads();
#pragma unroll
        for (int i = 0; i < 4; i++) {
            const int flat = i*1024 + t*4;
            *(float4*)&Bs[flat] = *(const float4*)(Bm + kb*32*128 + flat);
        }
        __syncthreads();
#pragma unroll
        for (int k = 0; k < 32; k++) {
            const float bv = Bs[k*128 + c];
#pragma unroll
            for (int i = 0; i < 4; i++)
                acc[i] += As[(rg*4+i)*128 + kb*32 + k] * bv;
        }
    }
    const float s0 = g_scal[0], s1 = g_scal[1];
#pragma unroll
    for (int i = 0; i < 4; i++) {
        const int idx = (blk*8 + rg*4 + i)*128 + c;
        float v = acc[i];
        if (mode == 0)       Cout[idx] = v;
        else if (mode == 1)  Cout[idx] = 1.5f*Cin[idx] - 0.5f*s0*v;
        else                 Cout[idx] = s1*v;
    }
}

__global__ void k_bias() {              // <<<1,256>>>  bias = M @ mean; split M -> bf16 hi/lo
    __shared__ float mn[128];
    const int t = threadIdx.x;
    if (t < 128) mn[t] = g_mean[t];
    __syncthreads();
    if (t < 128) {
        float s = 0.f;
        const float* Mrow = g_bufs[4] + t*Cc;
        for (int c = 0; c < Cc; c++) s += Mrow[c] * mn[c];
        g_bias[t] = s;
    }
    for (int idx = t; idx < 8192; idx += 256) {
        const float2 mv = *(const float2*)&g_bufs[4][idx*2];
        __nv_bfloat16 h0 = __float2bfloat16(mv.x), h1 = __float2bfloat16(mv.y);
        __nv_bfloat16 l0 = __float2bfloat16(mv.x - __bfloat162float(h0));
        __nv_bfloat16 l1 = __float2bfloat16(mv.y - __bfloat162float(h1));
        ((uint32_t*)g_Mh)[idx] = packbf(h0, h1);
        ((uint32_t*)g_Ml)[idx] = packbf(l0, l1);
    }
}

// =========================================================================
// k_transform: out[b,d,hw] = sum_c M[d,c] x[b,c,hw] - bias[d]
// D = Mh*Xh + Mh*Xl + Ml*Xh. M hi/lo staged in dynamic smem; X via ldmatrix.trans.
// dyn smem: Mh @0 (32KB), Ml @32768, hb @65536, lb @81920  (96KB total)
// =========================================================================
__global__ __launch_bounds__(256, 1) void k_transform(const float* __restrict__ x,
                                                      float* __restrict__ out) {
    extern __shared__ __align__(128) char dyn[];
    char* Mh_s = dyn;
    char* Ml_s = dyn + 32768;
    char* hb   = dyn + 65536;
    char* lb   = dyn + 81920;
    const int t = threadIdx.x, p = blockIdx.x;
    const int w = t >> 5, l = t & 31;

    // stage M hi/lo: row = d (256B rows), swizzle kb ^ ((row&7)<<4)
    for (int idx = t; idx < 8192; idx += 256) {
        const int row = idx >> 6;
        const uint32_t kb = (uint32_t)(idx & 63) * 4;
        const uint32_t off = (uint32_t)row * 256 + (kb ^ (uint32_t)((row & 7) << 4));
        *(uint32_t*)(Mh_s + off) = ((const uint32_t*)g_Mh)[idx];
        *(uint32_t*)(Ml_s + off) = ((const uint32_t*)g_Ml)[idx];
    }
    __syncthreads();

    const uint32_t mha = smem_u32(Mh_s), mla = smem_u32(Ml_s);
    const uint32_t hba = smem_u32(hb),   lba = smem_u32(lb);

    // per-thread fixed output rows + bias
    const int r0 = w * 16 + (l >> 2);
    const float bi0 = g_bias[r0], bi1 = g_bias[r0 + 8];

    const int t0  = p * 21 + min(p, 28);
    const int cnt = 21 + (p < 28 ? 1 : 0);

    for (int i = 0; i < cnt; i++) {
        load_tile(x, t0 + i, hb, lb, 0);
        __syncthreads();

        float d[8][4];
#pragma unroll
        for (int nb = 0; nb < 8; nb++)
#pragma unroll
            for (int q = 0; q < 4; q++) d[nb][q] = 0.f;

#pragma unroll
        for (int ks = 0; ks < 8; ks++) {
            const int arow = w*16 + (l & 15);
            const uint32_t akb = (uint32_t)(ks*32 + (l >> 4)*16);
            const uint32_t aoff = (uint32_t)arow * 256 + (akb ^ (uint32_t)((arow & 7) << 4));
            uint32_t ah[4], al[4];
            LDM_X4(ah[0], ah[1], ah[2], ah[3], mha + aoff);
            LDM_X4(al[0], al[1], al[2], al[3], mla + aoff);
#pragma unroll
            for (int nb = 0; nb < 8; nb++) {
                const uint32_t boff = SWZ((uint32_t)((ks*16 + (l & 15))*128 + nb*16));
                uint32_t bh0, bh1, bl0, bl1;
                LDM_X2T(bh0, bh1, hba + boff);
                LDM_X2T(bl0, bl1, lba + boff);
                MMA16816(d[nb], ah[0], ah[1], ah[2], ah[3], bh0, bh1);
                MMA16816(d[nb], ah[0], ah[1], ah[2], ah[3], bl0, bl1);
                MMA16816(d[nb], al[0], al[1], al[2], al[3], bh0, bh1);
            }
        }

        // store with bias subtract
        const int tj = t0 + i;
        const int b = tj / 49;
        const int hw0 = (tj - b * 49) * 64;
        float* ob = out + (size_t)b * Cc * HWn + hw0;
#pragma unroll
        for (int nb = 0; nb < 8; nb++) {
            const int n = nb*8 + (l & 3)*2;
            *(float2*)(ob + (size_t)r0*HWn + n)       = make_float2(d[nb][0]-bi0, d[nb][1]-bi0);
            *(float2*)(ob + (size_t)(r0+8)*HWn + n)   = make_float2(d[nb][2]-bi1, d[nb][3]-bi1);
        }
        __syncthreads();
    }
}

// =========================================================================
extern "C" void kernel_launch(void* const* d_in, const int* in_sizes, int n_in,
                              void* d_out, int out_size) {
    const float* x   = (const float*)d_in[0];
    const float* rot = (const float*)d_in[1];
    float* out = (float*)d_out;
    (void)in_sizes; (void)n_in; (void)out_size;

    cudaFuncSetAttribute(k_transform, cudaFuncAttributeMaxDynamicSharedMemorySize, 98304);

    k_cov<<<NCOV, 256>>>(x);
    k_meanred<<<1, 128>>>();
    k_sigred<<<128, 128>>>();
    k_trace_init<<<1, 256>>>();
    for (int it = 0; it < 5; it++) {
        k_mm<<<16, 256>>>(0, 0, 0, 1, 0, rot);   // T1 = P*P
        k_mm<<<16, 256>>>(1, 0, 0, 2, 0, rot);   // T2 = T1*P
        k_mm<<<16, 256>>>(2, 3, 0, 0, 1, rot);   // P  = 1.5P - 0.5*rTr*(T2*Sigma)
    }
    k_mm<<<16, 256>>>(5, 0, 0, 4, 2, rot);       // M = sqrt(rTr)*rot*P
    k_bias<<<1, 256>>>();
    k_transform<<<NCOV, 256, 98304>>>(x, out);
}

// round 11
// speedup vs baseline: 2.0812x; 1.4153x over previous
#include <cuda_runtime.h>
#include <cuda_bf16.h>
#include <cstdint>
#include <math.h>

#define Bn    64
#define Cc    128
#define HWn   3136
#define MTOT  (Bn*HWn)
#define NCOV  148
#define NNEW  32
#define EPSV  1e-5f

// ---------------- device scratch ----------------
__device__ float g_pS1[NCOV*Cc*Cc];
__device__ float g_pS2[NCOV*Cc*Cc];
__device__ float g_psum[NCOV*Cc];
__device__ float g_bufs[5][Cc*Cc];      // 0=P 1=T1/WV 2=T2/V 3=Sigma 4=M
__device__ float g_bias[Cc];
__device__ __align__(4) __nv_bfloat16 g_Mh[Cc*Cc];
__device__ __align__(4) __nv_bfloat16 g_Ml[Cc*Cc];
__device__ unsigned g_bar_ctr  = 0;
__device__ unsigned g_exit_ctr = 0;

// ---------------- helpers ----------------
__device__ __forceinline__ uint32_t smem_u32(const void* p) {
    uint32_t a;
    asm("{ .reg .u64 t; cvta.to.shared.u64 t, %1; cvt.u32.u64 %0, t; }" : "=r"(a) : "l"(p));
    return a;
}
#define SWZ(x) ((x) ^ (((x) >> 3) & 0x70))

#define LDM_X4(r0,r1,r2,r3,addr) \
    asm volatile("ldmatrix.sync.aligned.m8n8.x4.shared.b16 {%0,%1,%2,%3}, [%4];" \
        : "=r"(r0),"=r"(r1),"=r"(r2),"=r"(r3) : "r"(addr))
#define LDM_X2(r0,r1,addr) \
    asm volatile("ldmatrix.sync.aligned.m8n8.x2.shared.b16 {%0,%1}, [%2];" \
        : "=r"(r0),"=r"(r1) : "r"(addr))
#define LDM_X2T(r0,r1,addr) \
    asm volatile("ldmatrix.sync.aligned.m8n8.x2.trans.shared.b16 {%0,%1}, [%2];" \
        : "=r"(r0),"=r"(r1) : "r"(addr))
#define MMA16816(d,a0,a1,a2,a3,b0,b1) \
    asm volatile("mma.sync.aligned.m16n8k16.row.col.f32.bf16.bf16.f32 " \
        "{%0,%1,%2,%3}, {%4,%5,%6,%7}, {%8,%9}, {%0,%1,%2,%3};" \
        : "+f"((d)[0]),"+f"((d)[1]),"+f"((d)[2]),"+f"((d)[3]) \
        : "r"(a0),"r"(a1),"r"(a2),"r"(a3),"r"(b0),"r"(b1))

__device__ __forceinline__ uint32_t packbf(__nv_bfloat16 a, __nv_bfloat16 b) {
    return ((uint32_t)__bfloat16_as_ushort(b) << 16) | (uint32_t)__bfloat16_as_ushort(a);
}

// raw gmem loads for one 128x64 tile (8 float4 per thread)
__device__ __forceinline__ void load_raw(const float* __restrict__ x, int ti, float4* raw) {
    const int b = ti / 49;
    const int hw0 = (ti - b * 49) * 64;
    const int t = threadIdx.x;
#pragma unroll
    for (int i = 0; i < 8; i++) {
        const int q = i * 256 + t;
        const int r = q >> 4, c4 = q & 15;
        raw[i] = *(const float4*)(x + ((size_t)(b * Cc + r)) * HWn + hw0 + c4 * 4);
    }
}

// convert raw fp32 -> bf16 hi/lo, store to swizzled smem tile; optional channel sums
__device__ __forceinline__ void convert_store(const float4* raw, char* hb, char* lb, float* sacc) {
    const int t = threadIdx.x;
#pragma unroll
    for (int i = 0; i < 8; i++) {
        const int q = i * 256 + t;
        const int r = q >> 4, c4 = q & 15;
        const float4 v = raw[i];
        if (sacc) sacc[i] += (v.x + v.y) + (v.z + v.w);
        __nv_bfloat16 h0 = __float2bfloat16(v.x), h1 = __float2bfloat16(v.y);
        __nv_bfloat16 h2 = __float2bfloat16(v.z), h3 = __float2bfloat16(v.w);
        uint2 ph; ph.x = packbf(h0, h1); ph.y = packbf(h2, h3);
        __nv_bfloat16 l0 = __float2bfloat16(v.x - __bfloat162float(h0));
        __nv_bfloat16 l1 = __float2bfloat16(v.y - __bfloat162float(h1));
        __nv_bfloat16 l2 = __float2bfloat16(v.z - __bfloat162float(h2));
        __nv_bfloat16 l3 = __float2bfloat16(v.w - __bfloat162float(h3));
        uint2 pl; pl.x = packbf(l0, l1); pl.y = packbf(l2, l3);
        const uint32_t off = SWZ((uint32_t)(r * 128 + c4 * 8));
        *(uint2*)(hb + off) = ph;
        *(uint2*)(lb + off) = pl;
    }
}

// =========================================================================
// k_cov: HMMA SYRK partials, double-buffered tiles.
// warps 0-3: S1 = Xh*Xh^T, warps 4-7: S2 = Xh*Xl^T (32 rows x 128 cols each)
// dyn smem: hb0@0 lb0@16K hb1@32K lb1@48K (64KB)
// =========================================================================
__global__ __launch_bounds__(256, 1) void k_cov(const float* __restrict__ x) {
    extern __shared__ __align__(128) char dyn[];
    const int t = threadIdx.x, p = blockIdx.x;
    const int w = t >> 5, l = t & 31;

    const int t0  = p * 21 + min(p, 28);
    const int cnt = 21 + (p < 28 ? 1 : 0);

    float sacc[8];
#pragma unroll
    for (int i = 0; i < 8; i++) sacc[i] = 0.f;

    float d[2][16][4];
#pragma unroll
    for (int b2 = 0; b2 < 2; b2++)
#pragma unroll
        for (int j = 0; j < 16; j++)
#pragma unroll
            for (int q = 0; q < 4; q++) d[b2][j][q] = 0.f;

    const int rbase = (w & 3) * 32;
    float4 raw[8];

    load_raw(x, t0, raw);
    convert_store(raw, dyn, dyn + 16384, sacc);
    __syncthreads();

    for (int i = 0; i < cnt; i++) {
        const int cur = i & 1;
        char* hb = dyn + cur * 32768;
        const uint32_t hba = smem_u32(hb);
        const uint32_t bba = (w >= 4) ? (hba + 16384u) : hba;

        if (i + 1 < cnt) load_raw(x, t0 + i + 1, raw);   // in-flight during MMA

#pragma unroll
        for (int ks = 0; ks < 4; ks++) {
            uint32_t a[2][4];
#pragma unroll
            for (int blk = 0; blk < 2; blk++) {
                const uint32_t ao = hba + SWZ((uint32_t)((rbase + blk*16 + (l & 15))*128
                                              + ks*32 + (l >> 4)*16));
                LDM_X4(a[blk][0], a[blk][1], a[blk][2], a[blk][3], ao);
            }
#pragma unroll
            for (int jb = 0; jb < 16; jb++) {
                uint32_t b0, b1;
                const uint32_t bo = bba + SWZ((uint32_t)((jb*8 + (l & 7))*128
                                              + ks*32 + ((l >> 3) & 1)*16));
                LDM_X2(b0, b1, bo);
                MMA16816(d[0][jb], a[0][0], a[0][1], a[0][2], a[0][3], b0, b1);
                MMA16816(d[1][jb], a[1][0], a[1][1], a[1][2], a[1][3], b0, b1);
            }
        }

        if (i + 1 < cnt) {
            char* nh = dyn + ((i + 1) & 1) * 32768;
            convert_store(raw, nh, nh + 16384, sacc);
        }
        __syncthreads();
    }

    // write partials
    float* dst = ((w >= 4) ? g_pS2 : g_pS1) + (size_t)p * 16384;
#pragma unroll
    for (int blk = 0; blk < 2; blk++) {
#pragma unroll
        for (int jb = 0; jb < 16; jb++) {
            const int r0 = rbase + blk*16 + (l >> 2);
            const int c  = jb*8 + (l & 3)*2;
            *(float2*)&dst[r0*128 + c]       = make_float2(d[blk][jb][0], d[blk][jb][1]);
            *(float2*)&dst[(r0 + 8)*128 + c] = make_float2(d[blk][jb][2], d[blk][jb][3]);
        }
    }

    // mean partials
#pragma unroll
    for (int i = 0; i < 8; i++) {
#pragma unroll
        for (int off = 8; off > 0; off >>= 1)
            sacc[i] += __shfl_down_sync(0xffffffffu, sacc[i], off, 16);
    }
    if ((t & 15) == 0) {
#pragma unroll
        for (int i = 0; i < 8; i++) g_psum[p * Cc + i * 16 + (t >> 4)] = sacc[i];
    }
}

// =========================================================================
// k_newton: single persistent launch (32 CTAs) with grid barrier.
// Fuses: mean, Sigma assembly, trace, 16 fp32 matmuls, bias, M bf16 split.
// =========================================================================
__device__ __forceinline__ void gbar(unsigned phn) {
    __threadfence();
    __syncthreads();
    if (threadIdx.x == 0) {
        atomicAdd(&g_bar_ctr, 1u);
        const unsigned tgt = 32u * phn;
        while (atomicAdd(&g_bar_ctr, 0u) < tgt) { }
    }
    __syncthreads();
}

__device__ __forceinline__ void mm_phase(int p, const float* __restrict__ A,
        const float* __restrict__ B, const float* __restrict__ Cin,
        float* __restrict__ Cout, int mode, float c0, float c1,
        float* Bs, float* As) {
    const int t = threadIdx.x;
    ((float2*)As)[t] = __ldcg((const float2*)(A + p * 512) + t);
    const int c = t & 127;
    const int rr = (t >> 7) * 2;
    float a0 = 0.f, a1 = 0.f;
    for (int kb = 0; kb < 4; kb++) {
        __syncthreads();
#pragma unroll
        for (int i = 0; i < 4; i++)
            ((float4*)Bs)[i * 256 + t] = __ldcg((const float4*)(B + kb * 4096) + i * 256 + t);
        __syncthreads();
#pragma unroll 8
        for (int k = 0; k < 32; k++) {
            const float bv = Bs[k * 128 + c];
            a0 += As[rr * 128 + kb * 32 + k] * bv;
            a1 += As[rr * 128 + 128 + kb * 32 + k] * bv;
        }
    }
    const int e0 = p * 512 + rr * 128 + c;
    if (mode == 0)      { Cout[e0] = a0; Cout[e0 + 128] = a1; }
    else if (mode == 1) { Cout[e0]       = 1.5f * __ldcg(Cin + e0)       - 0.5f * c0 * a0;
                          Cout[e0 + 128] = 1.5f * __ldcg(Cin + e0 + 128) - 0.5f * c0 * a1; }
    else                { Cout[e0] = c1 * a0; Cout[e0 + 128] = c1 * a1; }
}

__global__ __launch_bounds__(256) void k_newton(const float* __restrict__ rot) {
    __shared__ float Bs[32 * 128];
    __shared__ float As[512];
    __shared__ float mn[128];
    __shared__ float red[128];
    __shared__ float bred[256];
    const int t = threadIdx.x, p = blockIdx.x;

    if (t < 128) {
        float s = 0.f;
        for (int q = 0; q < NCOV; q++) s += __ldcg(&g_psum[q * Cc + t]);
        mn[t] = s * (1.f / (float)MTOT);
    }
    // phase 1: WV = sum(S1+S2), V = sum(S2)
    {
        const int e0 = p * 512 + t * 2;
        float w0 = 0.f, w1 = 0.f, v0 = 0.f, v1 = 0.f;
        for (int q = 0; q < NCOV; q++) {
            const float2 a = __ldcg((const float2*)(g_pS1 + (size_t)q * 16384 + e0));
            const float2 b = __ldcg((const float2*)(g_pS2 + (size_t)q * 16384 + e0));
            w0 += a.x; w1 += a.y; v0 += b.x; v1 += b.y;
        }
        *(float2*)&g_bufs[1][e0] = make_float2(w0 + v0, w1 + v1);
        *(float2*)&g_bufs[2][e0] = make_float2(v0, v1);
    }
    gbar(1);
    // phase 2: Sigma = (WV + V^T)/m - mean mean^T + eps I
#pragma unroll
    for (int u = 0; u < 2; u++) {
        const int e = p * 512 + t * 2 + u;
        const int i = e >> 7, j = e & 127;
        float v = (__ldcg(&g_bufs[1][e]) + __ldcg(&g_bufs[2][j * 128 + i])) * (1.f / (float)MTOT)
                  - mn[i] * mn[j];
        if (i == j) v += EPSV;
        g_bufs[3][e] = v;
    }
    gbar(2);
    // trace (redundant per CTA) + P = I
    if (t < 128) red[t] = __ldcg(&g_bufs[3][t * 129]);
    __syncthreads();
    for (int s = 64; s > 0; s >>= 1) {
        if (t < s) red[t] += red[t + s];
        __syncthreads();
    }
    const float rTr = 1.f / red[0];
    const float sc1 = sqrtf(rTr);
#pragma unroll
    for (int u = 0; u < 2; u++) {
        const int e = p * 512 + t * 2 + u;
        g_bufs[0][e] = ((e >> 7) == (e & 127)) ? 1.f : 0.f;
    }
    gbar(3);
    unsigned phn = 3;
    for (int it = 0; it < 5; it++) {
        mm_phase(p, g_bufs[0], g_bufs[0], 0,          g_bufs[1], 0, 0.f, 0.f, Bs, As); gbar(++phn);
        mm_phase(p, g_bufs[1], g_bufs[0], 0,          g_bufs[2], 0, 0.f, 0.f, Bs, As); gbar(++phn);
        mm_phase(p, g_bufs[2], g_bufs[3], g_bufs[0],  g_bufs[0], 1, rTr, 0.f, Bs, As); gbar(++phn);
    }
    mm_phase(p, rot, g_bufs[0], 0, g_bufs[4], 2, 0.f, sc1, Bs, As); gbar(++phn);

    // epilogue (own 4 rows): bias + M bf16 split
    {
        const int r = p * 4 + (t >> 6);
        const int cl = t & 63;
        bred[t] = __ldcg(&g_bufs[4][r * 128 + cl]) * mn[cl]
                + __ldcg(&g_bufs[4][r * 128 + 64 + cl]) * mn[64 + cl];
        __syncthreads();
        for (int s = 32; s > 0; s >>= 1) {
            if ((t & 63) < s) bred[t] += bred[t + s];
            __syncthreads();
        }
        if ((t & 63) == 0) g_bias[r] = bred[t];
    }
    {
        const float2 mv = __ldcg((const float2*)&g_bufs[4][p * 512 + t * 2]);
        __nv_bfloat16 h0 = __float2bfloat16(mv.x), h1 = __float2bfloat16(mv.y);
        __nv_bfloat16 l0 = __float2bfloat16(mv.x - __bfloat162float(h0));
        __nv_bfloat16 l1 = __float2bfloat16(mv.y - __bfloat162float(h1));
        ((uint32_t*)g_Mh)[p * 256 + t] = packbf(h0, h1);
        ((uint32_t*)g_Ml)[p * 256 + t] = packbf(l0, l1);
    }
    __syncthreads();
    if (t == 0) {
        __threadfence();
        const unsigned v = atomicAdd(&g_exit_ctr, 1u);
        if (v == 31u) { g_bar_ctr = 0u; g_exit_ctr = 0u; __threadfence(); }
    }
}

// =========================================================================
// k_transform: D = Mh*Xh + Mh*Xl + Ml*Xh - bias. M frags hoisted to regs,
// double-buffered X tiles.
// dyn smem: Mstage@0 (32KB), hb0@32K lb0@48K hb1@64K lb1@80K (96KB)
// =========================================================================
__global__ __launch_bounds__(256, 1) void k_transform(const float* __restrict__ x,
                                                      float* __restrict__ out) {
    extern __shared__ __align__(128) char dyn[];
    char* Ms   = dyn;
    char* tile = dyn + 32768;
    const int t = threadIdx.x, p = blockIdx.x;
    const int w = t >> 5, l = t & 31;

    // ---- hoist M fragments: stage Mh, ldmatrix, then Ml ----
    uint32_t ah[8][4], al[8][4];
    const uint32_t msa = smem_u32(Ms);
    const int arow = w * 16 + (l & 15);
#pragma unroll
    for (int pass = 0; pass < 2; pass++) {
        const uint32_t* src = (const uint32_t*)(pass ? g_Ml : g_Mh);
        for (int idx = t; idx < 8192; idx += 256) {
            const int row = idx >> 6;
            const uint32_t kb = (uint32_t)(idx & 63) * 4;
            *(uint32_t*)(Ms + (uint32_t)row * 256 + (kb ^ (uint32_t)((row & 7) << 4))) = src[idx];
        }
        __syncthreads();
#pragma unroll
        for (int ks = 0; ks < 8; ks++) {
            const uint32_t akb = (uint32_t)(ks*32 + (l >> 4)*16);
            const uint32_t aoff = (uint32_t)arow * 256 + (akb ^ (uint32_t)((arow & 7) << 4));
            if (pass == 0) { LDM_X4(ah[ks][0], ah[ks][1], ah[ks][2], ah[ks][3], msa + aoff); }
            else           { LDM_X4(al[ks][0], al[ks][1], al[ks][2], al[ks][3], msa + aoff); }
        }
        __syncthreads();
    }

    const int r0 = w * 16 + (l >> 2);
    const float bi0 = g_bias[r0], bi1 = g_bias[r0 + 8];

    const int t0  = p * 21 + min(p, 28);
    const int cnt = 21 + (p < 28 ? 1 : 0);
    float4 raw[8];

    load_raw(x, t0, raw);
    convert_store(raw, tile, tile + 16384, 0);
    __syncthreads();

    for (int i = 0; i < cnt; i++) {
        const int cur = i & 1;
        char* hb = tile + cur * 32768;
        const uint32_t hba = smem_u32(hb);
        const uint32_t lba = hba + 16384u;

        if (i + 1 < cnt) load_raw(x, t0 + i + 1, raw);

        float d[8][4];
#pragma unroll
        for (int nb = 0; nb < 8; nb++)
#pragma unroll
            for (int q = 0; q < 4; q++) d[nb][q] = 0.f;

#pragma unroll
        for (int ks = 0; ks < 8; ks++) {
#pragma unroll
            for (int nb = 0; nb < 8; nb++) {
                const uint32_t boff = SWZ((uint32_t)((ks*16 + (l & 15))*128 + nb*16));
                uint32_t bh0, bh1, bl0, bl1;
                LDM_X2T(bh0, bh1, hba + boff);
                LDM_X2T(bl0, bl1, lba + boff);
                MMA16816(d[nb], ah[ks][0], ah[ks][1], ah[ks][2], ah[ks][3], bh0, bh1);
                MMA16816(d[nb], ah[ks][0], ah[ks][1], ah[ks][2], ah[ks][3], bl0, bl1);
                MMA16816(d[nb], al[ks][0], al[ks][1], al[ks][2], al[ks][3], bh0, bh1);
            }
        }

        // store with bias subtract
        const int tj = t0 + i;
        const int b = tj / 49;
        const int hw0 = (tj - b * 49) * 64;
        float* ob = out + (size_t)b * Cc * HWn + hw0;
#pragma unroll
        for (int nb = 0; nb < 8; nb++) {
            const int n = nb*8 + (l & 3)*2;
            *(float2*)(ob + (size_t)r0*HWn + n)     = make_float2(d[nb][0]-bi0, d[nb][1]-bi0);
            *(float2*)(ob + (size_t)(r0+8)*HWn + n) = make_float2(d[nb][2]-bi1, d[nb][3]-bi1);
        }

        if (i + 1 < cnt) {
            char* nh = tile + ((i + 1) & 1) * 32768;
            convert_store(raw, nh, nh + 16384, 0);
        }
        __syncthreads();
    }
}

// =========================================================================
extern "C" void kernel_launch(void* const* d_in, const int* in_sizes, int n_in,
                              void* d_out, int out_size) {
    const float* x   = (const float*)d_in[0];
    const float* rot = (const float*)d_in[1];
    float* out = (float*)d_out;
    (void)in_sizes; (void)n_in; (void)out_size;

    cudaFuncSetAttribute(k_cov,       cudaFuncAttributeMaxDynamicSharedMemorySize, 65536);
    cudaFuncSetAttribute(k_transform, cudaFuncAttributeMaxDynamicSharedMemorySize, 98304);

    k_cov<<<NCOV, 256, 65536>>>(x);
    k_newton<<<NNEW, 256>>>(rot);
    k_transform<<<NCOV, 256, 98304>>>(x, out);
}

// round 12
// speedup vs baseline: 2.3166x; 1.1131x over previous
#include <cuda_runtime.h>
#include <cuda_bf16.h>
#include <cstdint>
#include <math.h>

#define Bn    64
#define Cc    128
#define HWn   3136
#define MTOT  (Bn*HWn)
#define NCOV  148
#define NNEW  32
#define EPSV  1e-5f

// ---------------- device scratch ----------------
__device__ float g_pS1[NCOV*Cc*Cc];
__device__ float g_pS2[NCOV*Cc*Cc];
__device__ float g_psum[NCOV*Cc];
__device__ float g_bufs[5][Cc*Cc];
__device__ float g_bias[Cc];
__device__ __align__(4) __nv_bfloat16 g_Mh[Cc*Cc];
__device__ __align__(4) __nv_bfloat16 g_Ml[Cc*Cc];
__device__ unsigned g_bar_ctr  = 0;
__device__ unsigned g_exit_ctr = 0;

// ---------------- helpers ----------------
__device__ __forceinline__ uint32_t smem_u32(const void* p) {
    uint32_t a;
    asm("{ .reg .u64 t; cvta.to.shared.u64 t, %1; cvt.u32.u64 %0, t; }" : "=r"(a) : "l"(p));
    return a;
}
#define SWZ(x) ((x) ^ (((x) >> 3) & 0x70))

#define LDM_X4(r0,r1,r2,r3,addr) \
    asm volatile("ldmatrix.sync.aligned.m8n8.x4.shared.b16 {%0,%1,%2,%3}, [%4];" \
        : "=r"(r0),"=r"(r1),"=r"(r2),"=r"(r3) : "r"(addr))
#define LDM_X4T(r0,r1,r2,r3,addr) \
    asm volatile("ldmatrix.sync.aligned.m8n8.x4.trans.shared.b16 {%0,%1,%2,%3}, [%4];" \
        : "=r"(r0),"=r"(r1),"=r"(r2),"=r"(r3) : "r"(addr))
#define MMA16816(d,a0,a1,a2,a3,b0,b1) \
    asm volatile("mma.sync.aligned.m16n8k16.row.col.f32.bf16.bf16.f32 " \
        "{%0,%1,%2,%3}, {%4,%5,%6,%7}, {%8,%9}, {%0,%1,%2,%3};" \
        : "+f"((d)[0]),"+f"((d)[1]),"+f"((d)[2]),"+f"((d)[3]) \
        : "r"(a0),"r"(a1),"r"(a2),"r"(a3),"r"(b0),"r"(b1))

__device__ __forceinline__ uint32_t packbf(__nv_bfloat16 a, __nv_bfloat16 b) {
    return ((uint32_t)__bfloat16_as_ushort(b) << 16) | (uint32_t)__bfloat16_as_ushort(a);
}

// 512-thread variants: 4 float4 per thread per 128x64 tile
__device__ __forceinline__ void load_raw(const float* __restrict__ x, int ti, float4* raw) {
    const int b = ti / 49;
    const int hw0 = (ti - b * 49) * 64;
    const int t = threadIdx.x;
#pragma unroll
    for (int i = 0; i < 4; i++) {
        const int q = i * 512 + t;
        const int r = q >> 4, c4 = q & 15;
        raw[i] = *(const float4*)(x + ((size_t)(b * Cc + r)) * HWn + hw0 + c4 * 4);
    }
}

__device__ __forceinline__ void convert_store(const float4* raw, char* hb, char* lb, float* sacc) {
    const int t = threadIdx.x;
#pragma unroll
    for (int i = 0; i < 4; i++) {
        const int q = i * 512 + t;
        const int r = q >> 4, c4 = q & 15;
        const float4 v = raw[i];
        if (sacc) sacc[i] += (v.x + v.y) + (v.z + v.w);
        __nv_bfloat16 h0 = __float2bfloat16(v.x), h1 = __float2bfloat16(v.y);
        __nv_bfloat16 h2 = __float2bfloat16(v.z), h3 = __float2bfloat16(v.w);
        uint2 ph; ph.x = packbf(h0, h1); ph.y = packbf(h2, h3);
        __nv_bfloat16 l0 = __float2bfloat16(v.x - __bfloat162float(h0));
        __nv_bfloat16 l1 = __float2bfloat16(v.y - __bfloat162float(h1));
        __nv_bfloat16 l2 = __float2bfloat16(v.z - __bfloat162float(h2));
        __nv_bfloat16 l3 = __float2bfloat16(v.w - __bfloat162float(h3));
        uint2 pl; pl.x = packbf(l0, l1); pl.y = packbf(l2, l3);
        const uint32_t off = SWZ((uint32_t)(r * 128 + c4 * 8));
        *(uint2*)(hb + off) = ph;
        *(uint2*)(lb + off) = pl;
    }
}

// =========================================================================
// k_cov (512 threads, 16 warps): warps 0-7: S1 = Xh*Xh^T, warps 8-15: S2 =
// Xh*Xl^T. Warp tile 32 rows x 64 cols. Double-buffered tiles.
// dyn smem: hb0@0 lb0@16K hb1@32K lb1@48K (64KB)
// =========================================================================
__global__ __launch_bounds__(512, 1) void k_cov(const float* __restrict__ x) {
    extern __shared__ __align__(128) char dyn[];
    const int t = threadIdx.x, p = blockIdx.x;
    const int w = t >> 5, l = t & 31;
    const int w4 = w & 7;
    const int rbase = (w4 & 3) * 32;
    const int cblk  = (w4 >> 2) * 8;          // col-block base (units of 8)
    const bool is2 = (w >= 8);

    const int t0  = p * 21 + min(p, 28);
    const int cnt = 21 + (p < 28 ? 1 : 0);

    float sacc[4] = {0.f, 0.f, 0.f, 0.f};
    float d[2][8][4];
#pragma unroll
    for (int b2 = 0; b2 < 2; b2++)
#pragma unroll
        for (int j = 0; j < 8; j++)
#pragma unroll
            for (int q = 0; q < 4; q++) d[b2][j][q] = 0.f;

    float4 raw[4];
    load_raw(x, t0, raw);
    convert_store(raw, dyn, dyn + 16384, sacc);
    __syncthreads();

    for (int i = 0; i < cnt; i++) {
        const uint32_t hba = smem_u32(dyn + (i & 1) * 32768);
        const uint32_t bba = is2 ? (hba + 16384u) : hba;

        if (i + 1 < cnt) load_raw(x, t0 + i + 1, raw);

#pragma unroll
        for (int ks = 0; ks < 4; ks++) {
            uint32_t a[2][4];
#pragma unroll
            for (int blk = 0; blk < 2; blk++) {
                const uint32_t ao = hba + SWZ((uint32_t)((rbase + blk*16 + (l & 15))*128
                                              + ks*32 + (l >> 4)*16));
                LDM_X4(a[blk][0], a[blk][1], a[blk][2], a[blk][3], ao);
            }
#pragma unroll
            for (int jbp = 0; jbp < 4; jbp++) {
                uint32_t b0, b1, b2, b3;
                const uint32_t bo = bba + SWZ((uint32_t)(((cblk + jbp*2 + (l >> 4))*8
                                              + (l & 7))*128 + ks*32 + ((l >> 3) & 1)*16));
                LDM_X4(b0, b1, b2, b3, bo);
                MMA16816(d[0][jbp*2],   a[0][0],a[0][1],a[0][2],a[0][3], b0, b1);
                MMA16816(d[1][jbp*2],   a[1][0],a[1][1],a[1][2],a[1][3], b0, b1);
                MMA16816(d[0][jbp*2+1], a[0][0],a[0][1],a[0][2],a[0][3], b2, b3);
                MMA16816(d[1][jbp*2+1], a[1][0],a[1][1],a[1][2],a[1][3], b2, b3);
            }
        }

        if (i + 1 < cnt) {
            char* nh = dyn + ((i + 1) & 1) * 32768;
            convert_store(raw, nh, nh + 16384, sacc);
        }
        __syncthreads();
    }

    // write partials
    float* dst = (is2 ? g_pS2 : g_pS1) + (size_t)p * 16384;
#pragma unroll
    for (int blk = 0; blk < 2; blk++) {
#pragma unroll
        for (int jb = 0; jb < 8; jb++) {
            const int r0 = rbase + blk*16 + (l >> 2);
            const int c  = cblk*8 + jb*8 + (l & 3)*2;
            *(float2*)&dst[r0*128 + c]       = make_float2(d[blk][jb][0], d[blk][jb][1]);
            *(float2*)&dst[(r0 + 8)*128 + c] = make_float2(d[blk][jb][2], d[blk][jb][3]);
        }
    }

    // mean partials: groups of 16 threads share row i*32 + (t>>4)
#pragma unroll
    for (int i = 0; i < 4; i++) {
#pragma unroll
        for (int off = 8; off > 0; off >>= 1)
            sacc[i] += __shfl_down_sync(0xffffffffu, sacc[i], off, 16);
    }
    if ((t & 15) == 0) {
#pragma unroll
        for (int i = 0; i < 4; i++) g_psum[p * Cc + i * 32 + (t >> 4)] = sacc[i];
    }
}

// =========================================================================
// k_newton: persistent 32 CTAs, coupled Newton-Schulz, 13 grid barriers.
//   Y0=SigmaN, Z0=I; T=3I-Z*Y; Y'=0.5*Y*T; Z'=0.5*T*Z; Z_k == P_k.
// =========================================================================
__device__ __forceinline__ void gbar(unsigned phn) {
    __threadfence();
    __syncthreads();
    if (threadIdx.x == 0) {
        atomicAdd(&g_bar_ctr, 1u);
        const unsigned tgt = 32u * phn;
        while (atomicAdd(&g_bar_ctr, 0u) < tgt) { }
    }
    __syncthreads();
}

// computes 4 rows [r0, r0+4) of C = op(A*B); 256 threads
__device__ __forceinline__ void mm4(int r0, const float* __restrict__ A,
        const float* __restrict__ B, float* __restrict__ C,
        int mode, float c0, float* Bs, float* As) {
    const int t = threadIdx.x;
    __syncthreads();                       // protect As/Bs from prior call
    ((float2*)As)[t] = __ldcg((const float2*)(A + r0 * 128) + t);
    const int c = t & 127;
    const int rr = (t >> 7) * 2;
    float a0 = 0.f, a1 = 0.f;
    for (int kb = 0; kb < 4; kb++) {
        __syncthreads();
#pragma unroll
        for (int i = 0; i < 4; i++)
            ((float4*)Bs)[i * 256 + t] = __ldcg((const float4*)(B + kb * 4096) + i * 256 + t);
        __syncthreads();
#pragma unroll 8
        for (int k = 0; k < 32; k++) {
            const float bv = Bs[k * 128 + c];
            a0 += As[rr * 128 + kb * 32 + k] * bv;
            a1 += As[(rr + 1) * 128 + kb * 32 + k] * bv;
        }
    }
    const int i0 = r0 + rr;
    const int e0 = i0 * 128 + c;
    if (mode == 4)      { C[e0] = 0.5f * a0; C[e0 + 128] = 0.5f * a1; }
    else if (mode == 3) { C[e0]       = ((i0 == c)     ? 3.f : 0.f) - a0;
                          C[e0 + 128] = ((i0 + 1 == c) ? 3.f : 0.f) - a1; }
    else                { C[e0] = c0 * a0; C[e0 + 128] = c0 * a1; }
}

__global__ __launch_bounds__(256) void k_newton(const float* __restrict__ rot) {
    __shared__ float Bs[32 * 128];
    __shared__ float As[512];
    __shared__ float mn[128];
    __shared__ float red[128];
    __shared__ float bred[256];
    const int t = threadIdx.x, p = blockIdx.x;

    if (t < 128) {
        float s = 0.f;
        for (int q = 0; q < NCOV; q++) s += __ldcg(&g_psum[q * Cc + t]);
        mn[t] = s * (1.f / (float)MTOT);
    }
    // ph1: WV = sum(S1+S2) -> bufs[1], V = sum(S2) -> bufs[2]
    {
        const int e0 = p * 512 + t * 2;
        float w0 = 0.f, w1 = 0.f, v0 = 0.f, v1 = 0.f;
        for (int q = 0; q < NCOV; q++) {
            const float2 a = __ldcg((const float2*)(g_pS1 + (size_t)q * 16384 + e0));
            const float2 b = __ldcg((const float2*)(g_pS2 + (size_t)q * 16384 + e0));
            w0 += a.x; w1 += a.y; v0 += b.x; v1 += b.y;
        }
        *(float2*)&g_bufs[1][e0] = make_float2(w0 + v0, w1 + v1);
        *(float2*)&g_bufs[2][e0] = make_float2(v0, v1);
    }
    gbar(1);
    // ph2: Sigma = (WV + V^T)/m - mean mean^T + eps I  -> bufs[3]
#pragma unroll
    for (int u = 0; u < 2; u++) {
        const int e = p * 512 + t * 2 + u;
        const int i = e >> 7, j = e & 127;
        float v = (__ldcg(&g_bufs[1][e]) + __ldcg(&g_bufs[2][j * 128 + i])) * (1.f / (float)MTOT)
                  - mn[i] * mn[j];
        if (i == j) v += EPSV;
        g_bufs[3][e] = v;
    }
    gbar(2);
    // ph3: trace; Y0 = rTr*Sigma -> bufs[1]; T0 = 3I - Y0 -> bufs[2]; Z1 = 0.5*T0 -> bufs[0]
    if (t < 128) red[t] = __ldcg(&g_bufs[3][t * 129]);
    __syncthreads();
    for (int s = 64; s > 0; s >>= 1) {
        if (t < s) red[t] += red[t + s];
        __syncthreads();
    }
    const float rTr = 1.f / red[0];
    const float sc1 = sqrtf(rTr);
#pragma unroll
    for (int u = 0; u < 2; u++) {
        const int e = p * 512 + t * 2 + u;
        const float y0 = rTr * g_bufs[3][e];
        const float t0v = ((e >> 7) == (e & 127) ? 3.f : 0.f) - y0;
        g_bufs[1][e] = y0;
        g_bufs[2][e] = t0v;
        g_bufs[0][e] = 0.5f * t0v;
    }
    gbar(3);
    // ph4: Y1 = 0.5*Y0*T0 -> bufs[3]
    mm4(4 * p, g_bufs[1], g_bufs[2], g_bufs[3], 4, 0.f, Bs, As);
    gbar(4);

    // iters k=1..3: Z cycle {0,4,0,4}, Y cycle {3,1,3,1}
    const int Zc[4] = {0, 4, 0, 4};
    const int Yc[4] = {3, 1, 3, 1};
    unsigned bar = 4;
    for (int k = 0; k < 3; k++) {
        mm4(4 * p, g_bufs[Zc[k]], g_bufs[Yc[k]], g_bufs[2], 3, 0.f, Bs, As);   // T
        gbar(++bar);
        if (p < 16) {     // Y_{k+1} = 0.5*Y_k*T
            mm4(8 * p,     g_bufs[Yc[k]], g_bufs[2], g_bufs[Yc[k + 1]], 4, 0.f, Bs, As);
            mm4(8 * p + 4, g_bufs[Yc[k]], g_bufs[2], g_bufs[Yc[k + 1]], 4, 0.f, Bs, As);
        } else {          // Z_{k+1} = 0.5*T*Z_k
            const int q = p - 16;
            mm4(8 * q,     g_bufs[2], g_bufs[Zc[k]], g_bufs[Zc[k + 1]], 4, 0.f, Bs, As);
            mm4(8 * q + 4, g_bufs[2], g_bufs[Zc[k]], g_bufs[Zc[k + 1]], 4, 0.f, Bs, As);
        }
        gbar(++bar);
    }
    // final: T = 3I - Z4*Y4 (Z4@4, Y4@1); Z5 = 0.5*T*Z4 -> bufs[0]; M = sc1*rot*Z5 -> bufs[4]
    mm4(4 * p, g_bufs[4], g_bufs[1], g_bufs[2], 3, 0.f, Bs, As); gbar(++bar);  // 11
    mm4(4 * p, g_bufs[2], g_bufs[4], g_bufs[0], 4, 0.f, Bs, As); gbar(++bar);  // 12
    mm4(4 * p, rot,       g_bufs[0], g_bufs[4], 2, sc1, Bs, As); gbar(++bar);  // 13

    // epilogue: bias (own 4 rows) + M bf16 split
    {
        const int r = p * 4 + (t >> 6);
        const int cl = t & 63;
        bred[t] = __ldcg(&g_bufs[4][r * 128 + cl]) * mn[cl]
                + __ldcg(&g_bufs[4][r * 128 + 64 + cl]) * mn[64 + cl];
        __syncthreads();
        for (int s = 32; s > 0; s >>= 1) {
            if ((t & 63) < s) bred[t] += bred[t + s];
            __syncthreads();
        }
        if ((t & 63) == 0) g_bias[r] = bred[t];
    }
    {
        const float2 mv = __ldcg((const float2*)&g_bufs[4][p * 512 + t * 2]);
        __nv_bfloat16 h0 = __float2bfloat16(mv.x), h1 = __float2bfloat16(mv.y);
        __nv_bfloat16 l0 = __float2bfloat16(mv.x - __bfloat162float(h0));
        __nv_bfloat16 l1 = __float2bfloat16(mv.y - __bfloat162float(h1));
        ((uint32_t*)g_Mh)[p * 256 + t] = packbf(h0, h1);
        ((uint32_t*)g_Ml)[p * 256 + t] = packbf(l0, l1);
    }
    __syncthreads();
    if (t == 0) {
        __threadfence();
        const unsigned v = atomicAdd(&g_exit_ctr, 1u);
        if (v == 31u) { g_bar_ctr = 0u; g_exit_ctr = 0u; __threadfence(); }
    }
}

// =========================================================================
// k_transform (512 threads, 16 warps): D = Mh*Xh + Mh*Xl + Ml*Xh - bias.
// Warp tile 16 rows x 32 cols; M frags in regs; double-buffered X tiles.
// dyn smem: Mstage@0 (32KB), tiles@32K (64KB)  total 96KB
// =========================================================================
__global__ __launch_bounds__(512, 1) void k_transform(const float* __restrict__ x,
                                                      float* __restrict__ out) {
    extern __shared__ __align__(128) char dyn[];
    char* Ms   = dyn;
    char* tile = dyn + 32768;
    const int t = threadIdx.x, p = blockIdx.x;
    const int w = t >> 5, l = t & 31;
    const int rwarp = (w & 7) * 16;           // warp row base
    const int cbase = (w >> 3) * 32;          // warp col base

    // hoist M fragments
    uint32_t ah[8][4], al[8][4];
    const uint32_t msa = smem_u32(Ms);
    const int arow = rwarp + (l & 15);
#pragma unroll
    for (int pass = 0; pass < 2; pass++) {
        const uint32_t* src = (const uint32_t*)(pass ? g_Ml : g_Mh);
        for (int idx = t; idx < 8192; idx += 512) {
            const int row = idx >> 6;
            const uint32_t kb = (uint32_t)(idx & 63) * 4;
            *(uint32_t*)(Ms + (uint32_t)row * 256 + (kb ^ (uint32_t)((row & 7) << 4))) = src[idx];
        }
        __syncthreads();
#pragma unroll
        for (int ks = 0; ks < 8; ks++) {
            const uint32_t akb = (uint32_t)(ks*32 + (l >> 4)*16);
            const uint32_t aoff = (uint32_t)arow * 256 + (akb ^ (uint32_t)((arow & 7) << 4));
            if (pass == 0) { LDM_X4(ah[ks][0], ah[ks][1], ah[ks][2], ah[ks][3], msa + aoff); }
            else           { LDM_X4(al[ks][0], al[ks][1], al[ks][2], al[ks][3], msa + aoff); }
        }
        __syncthreads();
    }

    const int r0 = rwarp + (l >> 2);
    const float bi0 = g_bias[r0], bi1 = g_bias[r0 + 8];

    const int t0  = p * 21 + min(p, 28);
    const int cnt = 21 + (p < 28 ? 1 : 0);
    float4 raw[4];

    load_raw(x, t0, raw);
    convert_store(raw, tile, tile + 16384, 0);
    __syncthreads();

    for (int i = 0; i < cnt; i++) {
        const uint32_t hba = smem_u32(tile + (i & 1) * 32768);
        const uint32_t lba = hba + 16384u;

        if (i + 1 < cnt) load_raw(x, t0 + i + 1, raw);

        float d[4][4];
#pragma unroll
        for (int nb = 0; nb < 4; nb++)
#pragma unroll
            for (int q = 0; q < 4; q++) d[nb][q] = 0.f;

#pragma unroll
        for (int ks = 0; ks < 8; ks++) {
#pragma unroll
            for (int nbp = 0; nbp < 2; nbp++) {
                const uint32_t boff = SWZ((uint32_t)((ks*16 + (l & 15))*128
                                          + cbase*2 + nbp*32 + (l >> 4)*16));
                uint32_t bh0, bh1, bh2, bh3, bl0, bl1, bl2, bl3;
                LDM_X4T(bh0, bh1, bh2, bh3, hba + boff);
                LDM_X4T(bl0, bl1, bl2, bl3, lba + boff);
                MMA16816(d[nbp*2],   ah[ks][0],ah[ks][1],ah[ks][2],ah[ks][3], bh0, bh1);
                MMA16816(d[nbp*2],   ah[ks][0],ah[ks][1],ah[ks][2],ah[ks][3], bl0, bl1);
                MMA16816(d[nbp*2],   al[ks][0],al[ks][1],al[ks][2],al[ks][3], bh0, bh1);
                MMA16816(d[nbp*2+1], ah[ks][0],ah[ks][1],ah[ks][2],ah[ks][3], bh2, bh3);
                MMA16816(d[nbp*2+1], ah[ks][0],ah[ks][1],ah[ks][2],ah[ks][3], bl2, bl3);
                MMA16816(d[nbp*2+1], al[ks][0],al[ks][1],al[ks][2],al[ks][3], bh2, bh3);
            }
        }

        // store with bias subtract
        const int tj = t0 + i;
        const int b = tj / 49;
        const int hw0 = (tj - b * 49) * 64;
        float* ob = out + (size_t)b * Cc * HWn + hw0;
#pragma unroll
        for (int nb = 0; nb < 4; nb++) {
            const int n = cbase + nb*8 + (l & 3)*2;
            *(float2*)(ob + (size_t)r0*HWn + n)     = make_float2(d[nb][0]-bi0, d[nb][1]-bi0);
            *(float2*)(ob + (size_t)(r0+8)*HWn + n) = make_float2(d[nb][2]-bi1, d[nb][3]-bi1);
        }

        if (i + 1 < cnt) {
            char* nh = tile + ((i + 1) & 1) * 32768;
            convert_store(raw, nh, nh + 16384, 0);
        }
        __syncthreads();
    }
}

// =========================================================================
extern "C" void kernel_launch(void* const* d_in, const int* in_sizes, int n_in,
                              void* d_out, int out_size) {
    const float* x   = (const float*)d_in[0];
    const float* rot = (const float*)d_in[1];
    float* out = (float*)d_out;
    (void)in_sizes; (void)n_in; (void)out_size;

    cudaFuncSetAttribute(k_cov,       cudaFuncAttributeMaxDynamicSharedMemorySize, 65536);
    cudaFuncSetAttribute(k_transform, cudaFuncAttributeMaxDynamicSharedMemorySize, 98304);

    k_cov<<<NCOV, 512, 65536>>>(x);
    k_newton<<<NNEW, 256>>>(rot);
    k_transform<<<NCOV, 512, 98304>>>(x, out);
}